// round 4
// baseline (speedup 1.0000x reference)
#include <cuda_runtime.h>

#define BB 512
#define TT 200
#define MM 50
#define DKX 64
#define DVX 64
#define HHX 128
#define NSK 1000
#define NITEMS (BB*TT)

typedef unsigned long long u64;

// ---- packed f32x2 helpers ----
__device__ __forceinline__ u64 pk2(float lo, float hi) {
    u64 r; asm("mov.b64 %0,{%1,%2};" : "=l"(r) : "f"(lo), "f"(hi)); return r;
}
__device__ __forceinline__ u64 pkd(float x) {
    u64 r; asm("mov.b64 %0,{%1,%1};" : "=l"(r) : "f"(x)); return r;
}
__device__ __forceinline__ void up2(u64 v, float& lo, float& hi) {
    asm("mov.b64 {%0,%1},%2;" : "=f"(lo), "=f"(hi) : "l"(v));
}
__device__ __forceinline__ u64 ffma2(u64 a, u64 b, u64 c) {
    u64 d; asm("fma.rn.f32x2 %0,%1,%2,%3;" : "=l"(d) : "l"(a), "l"(b), "l"(c)); return d;
}

// ---- tables + scratch ----
__device__ float tw[NSK*MM];        // softmax(q_s . K^T) per skill
__device__ float te[2*NSK*DVX];     // sigmoid gate per interaction id
__device__ float ta[2*NSK*DVX];     // tanh add per interaction id
__device__ float qW[NSK*HHX];       // skill_embed[s] @ W1_top + b1
__device__ float g_read[NITEMS*DVX];

// ============================================================================
// Kernel 0: build tables. Roles by blockIdx (4 items per warp everywhere):
//   [0,32)    role A: tw     (32 skills/block)
//   [32,95)   role B: te/ta  (32 vis/block)
//   [95,127)  role C: qW     (32 skills/block)
// ============================================================================
__global__ __launch_bounds__(256) void k0_tables(
    const float* __restrict__ skill_embed,
    const float* __restrict__ key_memory,
    const float* __restrict__ interaction_embed,
    const float* __restrict__ erase_W,
    const float* __restrict__ erase_b,
    const float* __restrict__ add_W,
    const float* __restrict__ add_b,
    const float* __restrict__ fc1_W,
    const float* __restrict__ fc1_b)
{
    extern __shared__ float smem[];
    int tid  = threadIdx.x;
    int w    = tid >> 5;
    int lane = tid & 31;
    int bid  = blockIdx.x;

    if (bid < 32) {
        // ---------------- role A: attention softmax table (4 skills/warp) ----
        float* sKt = smem;            // [64][52] transposed
        float* sq  = sKt + DKX*52;    // [8 warps][256] layout [i*4+k]
        for (int idx = tid; idx < MM*DKX; idx += 256) {
            int m = idx / DKX, i = idx % DKX;
            sKt[i*52 + m] = key_memory[m*DKX + i];
        }
        __syncthreads();
        int sbase = bid*32 + w*4;
        float* mq = sq + w*256;
        #pragma unroll
        for (int k = 0; k < 4; k++) {
            int s = sbase + k; if (s >= NSK) s = NSK-1;
            mq[lane*4 + k]      = skill_embed[s*DKX + lane];
            mq[(lane+32)*4 + k] = skill_embed[s*DKX + lane+32];
        }
        __syncwarp();
        const bool v1 = (lane + 32) < MM;
        float d0[4] = {0,0,0,0}, d1[4] = {0,0,0,0};
        #pragma unroll 8
        for (int i = 0; i < DKX; i++) {
            float k0 = sKt[i*52 + lane];
            float k1 = sKt[i*52 + lane + 32];
            float4 q4 = *(const float4*)&mq[i*4];
            d0[0] = fmaf(q4.x, k0, d0[0]); d1[0] = fmaf(q4.x, k1, d1[0]);
            d0[1] = fmaf(q4.y, k0, d0[1]); d1[1] = fmaf(q4.y, k1, d1[1]);
            d0[2] = fmaf(q4.z, k0, d0[2]); d1[2] = fmaf(q4.z, k1, d1[2]);
            d0[3] = fmaf(q4.w, k0, d0[3]); d1[3] = fmaf(q4.w, k1, d1[3]);
        }
        #pragma unroll
        for (int k = 0; k < 4; k++) {
            float mx = fmaxf(d0[k], v1 ? d1[k] : -1e30f);
            #pragma unroll
            for (int off = 16; off > 0; off >>= 1)
                mx = fmaxf(mx, __shfl_xor_sync(0xffffffffu, mx, off));
            float x0 = __expf(d0[k] - mx);
            float x1 = v1 ? __expf(d1[k] - mx) : 0.f;
            float sm = x0 + x1;
            #pragma unroll
            for (int off = 16; off > 0; off >>= 1)
                sm += __shfl_xor_sync(0xffffffffu, sm, off);
            float inv = 1.f / sm;
            int s = sbase + k;
            if (s < NSK) {
                tw[s*MM + lane] = x0 * inv;
                if (v1) tw[s*MM + lane + 32] = x1 * inv;
            }
        }
    } else if (bid < 95) {
        // ---------------- role B: gate tables (4 vis/warp) ----------------
        float* seW = smem;            // [64*64]
        float* saW = seW + DKX*DVX;   // [64*64]
        float* sv  = saW + DKX*DVX;   // [8 warps][256]
        for (int idx = tid; idx < DKX*DVX; idx += 256) {
            seW[idx] = erase_W[idx];
            saW[idx] = add_W[idx];
        }
        __syncthreads();
        int vbase = (bid - 32)*32 + w*4;
        float* mv = sv + w*256;
        #pragma unroll
        for (int k = 0; k < 4; k++) {
            int vi = vbase + k; if (vi >= 2*NSK) vi = 2*NSK-1;
            mv[lane*4 + k]      = interaction_embed[vi*DVX + lane];
            mv[(lane+32)*4 + k] = interaction_embed[vi*DVX + lane+32];
        }
        __syncwarp();
        float eb0 = erase_b[lane], eb1 = erase_b[lane+32];
        float ab0 = add_b[lane],   ab1 = add_b[lane+32];
        float E0[4], E1[4], A0[4], A1[4];
        #pragma unroll
        for (int k = 0; k < 4; k++) { E0[k]=eb0; E1[k]=eb1; A0[k]=ab0; A1[k]=ab1; }
        #pragma unroll 4
        for (int i = 0; i < DVX; i++) {
            float w0 = seW[i*DVX + lane];
            float w1 = seW[i*DVX + lane+32];
            float u0 = saW[i*DVX + lane];
            float u1 = saW[i*DVX + lane+32];
            float4 v4 = *(const float4*)&mv[i*4];
            float vv[4] = {v4.x, v4.y, v4.z, v4.w};
            #pragma unroll
            for (int k = 0; k < 4; k++) {
                E0[k] = fmaf(vv[k], w0, E0[k]);
                E1[k] = fmaf(vv[k], w1, E1[k]);
                A0[k] = fmaf(vv[k], u0, A0[k]);
                A1[k] = fmaf(vv[k], u1, A1[k]);
            }
        }
        #pragma unroll
        for (int k = 0; k < 4; k++) {
            int vi = vbase + k;
            if (vi < 2*NSK) {
                te[vi*DVX + lane]    = 1.f/(1.f + __expf(-E0[k]));
                te[vi*DVX + lane+32] = 1.f/(1.f + __expf(-E1[k]));
                ta[vi*DVX + lane]    = tanhf(A0[k]);
                ta[vi*DVX + lane+32] = tanhf(A1[k]);
            }
        }
    } else {
        // ---------------- role C: qW table (4 skills/warp) ----------------
        float* sW1t = smem;            // [64][128] top rows of fc1_W
        float* sb1  = sW1t + 64*HHX;   // [128]
        float* sq   = sb1 + HHX;       // [8 warps][256]
        for (int idx = tid; idx < 64*HHX; idx += 256) sW1t[idx] = fc1_W[idx];
        if (tid < HHX) sb1[tid] = fc1_b[tid];
        __syncthreads();
        int sbase = (bid - 95)*32 + w*4;
        float* mq = sq + w*256;
        #pragma unroll
        for (int k = 0; k < 4; k++) {
            int s = sbase + k; if (s >= NSK) s = NSK-1;
            mq[lane*4 + k]      = skill_embed[s*DKX + lane];
            mq[(lane+32)*4 + k] = skill_embed[s*DKX + lane+32];
        }
        __syncwarp();
        u64 acc2[4][2];
        #pragma unroll
        for (int c = 0; c < 4; c++) {
            u64 bb = pkd(sb1[lane*4 + c]);
            acc2[c][0] = bb; acc2[c][1] = bb;
        }
        #pragma unroll 4
        for (int i = 0; i < DKX; i++) {
            u64 q01 = *(const u64*)&mq[i*4];
            u64 q23 = *(const u64*)&mq[i*4 + 2];
            float4 w4 = *(const float4*)&sW1t[i*HHX + lane*4];
            u64 wx = pkd(w4.x), wy = pkd(w4.y), wz = pkd(w4.z), wq = pkd(w4.w);
            acc2[0][0] = ffma2(q01, wx, acc2[0][0]);
            acc2[0][1] = ffma2(q23, wx, acc2[0][1]);
            acc2[1][0] = ffma2(q01, wy, acc2[1][0]);
            acc2[1][1] = ffma2(q23, wy, acc2[1][1]);
            acc2[2][0] = ffma2(q01, wz, acc2[2][0]);
            acc2[2][1] = ffma2(q23, wz, acc2[2][1]);
            acc2[3][0] = ffma2(q01, wq, acc2[3][0]);
            acc2[3][1] = ffma2(q23, wq, acc2[3][1]);
        }
        float A[4][4];
        #pragma unroll
        for (int c = 0; c < 4; c++) {
            up2(acc2[c][0], A[c][0], A[c][1]);
            up2(acc2[c][1], A[c][2], A[c][3]);
        }
        #pragma unroll
        for (int k = 0; k < 4; k++) {
            int s = sbase + k;
            if (s < NSK) {
                float4 o = make_float4(A[0][k], A[1][k], A[2][k], A[3][k]);
                *(float4*)&qW[s*HHX + lane*4] = o;
            }
        }
    }
}

// ============================================================================
// Kernel 2: sequential scan, WARP-AUTONOMOUS. One block per batch, 128 thr.
// Warp = 16 columns x 2 row-halves; lane holds 13 mem row-pairs (f32x2).
// Each warp stages its own w copy (own smem buffer) -> no __syncthreads in
// the loop. Tables prefetched 2 steps ahead to hide L2 latency.
// ============================================================================
__global__ __launch_bounds__(128) void k2_scan(
    const float* __restrict__ value_init,
    const int*   __restrict__ skill_seq,
    const int*   __restrict__ correct_seq)
{
    __shared__ __align__(8) float swp[4][2][52];
    __shared__ int ss[TT];
    __shared__ int svi[TT];
    int b    = blockIdx.x;
    int tid  = threadIdx.x;
    int wp   = tid >> 5;
    int lane = tid & 31;
    int col  = wp*16 + (lane >> 1);   // 0..63 DV column
    int h    = lane & 1;              // row-half
    const int base = b * TT;

    for (int i = tid; i < TT; i += 128) {
        int s = skill_seq[base + i];
        ss[i]  = s;
        svi[i] = s + correct_seq[base + i]*NSK;
    }
    // zero the pad pair (rows 50,51) in both buffers of this warp
    if (lane < 4) swp[wp][lane>>1][50 + (lane&1)] = 0.f;

    const int m0 = h * 13;            // h=0: pairs 0..12, h=1: pairs 13..25(pad)
    u64 mem[13];
    #pragma unroll
    for (int m = 0; m < 13; m++) {
        int p = m0 + m;
        mem[m] = (p < 25) ? pk2(value_init[(2*p)*DVX + col],
                                value_init[(2*p+1)*DVX + col]) : 0ull;
    }
    __syncthreads();   // once: ss/svi + pads visible

    // depth-2 prefetch pipeline
    int sA = ss[0], viA = svi[0];
    float w0A = tw[sA*MM + lane];
    float w1A = (lane < 18) ? tw[sA*MM + 32 + lane] : 0.f;
    float evA = te[viA*DVX + col];
    float avA = ta[viA*DVX + col];
    int sB = ss[1], viB = svi[1];
    float w0B = tw[sB*MM + lane];
    float w1B = (lane < 18) ? tw[sB*MM + 32 + lane] : 0.f;
    float evB = te[viB*DVX + col];
    float avB = ta[viB*DVX + col];

    for (int t = 0; t < TT; t++) {
        float* wb = &swp[wp][t & 1][0];
        wb[lane] = w0A;
        if (lane < 18) wb[32 + lane] = w1A;
        float e = evA, a = avA;
        w0A = w0B; w1A = w1B; evA = evB; avA = avB;
        __syncwarp();
        if (t + 2 < TT) {
            int sC = ss[t+2], viC = svi[t+2];
            w0B = tw[sC*MM + lane];
            w1B = (lane < 18) ? tw[sC*MM + 32 + lane] : 0.f;
            evB = te[viC*DVX + col];
            avB = ta[viC*DVX + col];
        }
        u64 nee = pkd(-e);
        u64 aa  = pkd(a);
        u64 r0 = 0ull, r1 = 0ull;
        #pragma unroll
        for (int m = 0; m < 13; m++) {
            u64 ww = *(const u64*)&wb[2*(m0 + m)];
            if (m & 1) r1 = ffma2(ww, mem[m], r1);
            else       r0 = ffma2(ww, mem[m], r0);
            u64 t1 = ffma2(mem[m], nee, aa);   // a - mem*e
            mem[m] = ffma2(ww, t1, mem[m]);    // mem + w*(a - mem*e)
        }
        float x0, x1, y0, y1;
        up2(r0, x0, x1); up2(r1, y0, y1);
        float r = (x0 + x1) + (y0 + y1);
        r += __shfl_xor_sync(0xffffffffu, r, 1);   // combine row-halves
        if (h == 0) g_read[(base + t)*DVX + col] = r;
    }
}

// ============================================================================
// Kernel 3: output MLP, read-half only. acc packed over OUTPUT pairs:
// weights come directly as u64 halves of LDS.128 (no dup MOVs); x staged
// pre-duplicated in smem via STS.64 of (r,r).
// ============================================================================
#define XS 18   // floats per j-row of staged x (8 dup-pairs + pad 2)

__global__ __launch_bounds__(256,3) void k3_mlp(
    const int*   __restrict__ skill_seq,
    const int*   __restrict__ correct_seq,
    const float* __restrict__ mask,
    const float* __restrict__ fc1_W,
    const float* __restrict__ fc2_W,
    const float* __restrict__ fc2_b,
    float*       __restrict__ out)
{
    extern __shared__ float smem[];
    float* sW1 = smem;                    // [64][128] = fc1_W rows 64..127
    float* sw2 = sW1 + 64*HHX;            // [128]
    float* sx  = sw2 + HHX;               // [8 warps][64*XS]

    int tid = threadIdx.x;
    for (int idx = tid; idx < 64*HHX; idx += 256) sW1[idx] = fc1_W[64*HHX + idx];
    if (tid < HHX) sw2[tid] = fc2_W[tid];
    __syncthreads();
    float b2 = fc2_b[0];

    int w    = tid >> 5;
    int lane = tid & 31;
    float* myx = sx + w * (64 * XS);
    float4 w2v = *(const float4*)&sw2[lane*4];

    const int nwarps  = gridDim.x * 8;
    const int ngroups = NITEMS / 8;

    for (int g = blockIdx.x*8 + w; g < ngroups; g += nwarps) {
        int base = g * 8;
        u64 acc[2][8];   // [output-pair p: c=lane*4+2p,+1][item k]
        #pragma unroll
        for (int k = 0; k < 8; k++) {
            int item = base + k;
            int s = skill_seq[item];
            float4 qk = *(const float4*)&qW[s*HHX + lane*4];
            acc[0][k] = pk2(qk.x, qk.y);
            acc[1][k] = pk2(qk.z, qk.w);
            float r0 = g_read[item*DVX + lane];
            float r1 = g_read[item*DVX + lane+32];
            *(u64*)&myx[lane*XS + 2*k]       = pk2(r0, r0);
            *(u64*)&myx[(lane+32)*XS + 2*k]  = pk2(r1, r1);
        }
        __syncwarp();

        #pragma unroll 4
        for (int j = 0; j < 64; j++) {
            float4 wv = *(const float4*)&sW1[j*HHX + lane*4];
            u64 w01 = pk2(wv.x, wv.y);
            u64 w23 = pk2(wv.z, wv.w);
            #pragma unroll
            for (int k = 0; k < 8; k++) {
                u64 xd = *(const u64*)&myx[j*XS + 2*k];
                acc[0][k] = ffma2(xd, w01, acc[0][k]);
                acc[1][k] = ffma2(xd, w23, acc[1][k]);
            }
        }

        float part[8];
        #pragma unroll
        for (int k = 0; k < 8; k++) {
            float h0, h1, h2, h3;
            up2(acc[0][k], h0, h1);
            up2(acc[1][k], h2, h3);
            float p;
            p = fmaxf(h0, 0.f) * w2v.x;
            p = fmaf(fmaxf(h1, 0.f), w2v.y, p);
            p = fmaf(fmaxf(h2, 0.f), w2v.z, p);
            p = fmaf(fmaxf(h3, 0.f), w2v.w, p);
            part[k] = p;
        }
        #pragma unroll
        for (int off = 16; off > 0; off >>= 1) {
            #pragma unroll
            for (int k = 0; k < 8; k++)
                part[k] += __shfl_xor_sync(0xffffffffu, part[k], off);
        }
        if (lane < 8) {
            int item = base + lane;
            float logit = part[lane] + b2;
            float p = 1.f / (1.f + __expf(-logit));
            float mk = mask[item];
            out[item]          = p * mk;
            out[NITEMS + item] = (float)correct_seq[item] * mk;
        }
        __syncwarp();
    }
}

// ============================================================================
extern "C" void kernel_launch(void* const* d_in, const int* in_sizes, int n_in,
                              void* d_out, int out_size) {
    const int*   skill_seq         = (const int*)  d_in[0];
    const int*   correct_seq       = (const int*)  d_in[1];
    const float* mask              = (const float*)d_in[2];
    const float* skill_embed       = (const float*)d_in[3];
    const float* key_memory        = (const float*)d_in[4];
    const float* value_init        = (const float*)d_in[5];
    const float* interaction_embed = (const float*)d_in[6];
    const float* erase_W           = (const float*)d_in[7];
    const float* erase_b           = (const float*)d_in[8];
    const float* add_W             = (const float*)d_in[9];
    const float* add_b             = (const float*)d_in[10];
    const float* fc1_W             = (const float*)d_in[11];
    const float* fc1_b             = (const float*)d_in[12];
    const float* fc2_W             = (const float*)d_in[13];
    const float* fc2_b             = (const float*)d_in[14];
    float* out = (float*)d_out;

    const int k0_smem = (64*HHX + HHX + 8*256) * sizeof(float);            // ~41.5 KB
    const int k3_smem = (64*HHX + HHX + 8*64*XS) * sizeof(float);          // ~68.5 KB
    cudaFuncSetAttribute(k3_mlp, cudaFuncAttributeMaxDynamicSharedMemorySize, k3_smem);

    k0_tables<<<127, 256, k0_smem>>>(skill_embed, key_memory, interaction_embed,
                                     erase_W, erase_b, add_W, add_b, fc1_W, fc1_b);
    k2_scan<<<BB, 128>>>(value_init, skill_seq, correct_seq);
    k3_mlp<<<444, 256, k3_smem>>>(skill_seq, correct_seq, mask,
                                  fc1_W, fc2_W, fc2_b, out);
}

// round 5
// speedup vs baseline: 1.3469x; 1.3469x over previous
#include <cuda_runtime.h>

#define BB 512
#define TT 200
#define MM 50
#define DKX 64
#define DVX 64
#define HHX 128
#define NSK 1000
#define NITEMS (BB*TT)

typedef unsigned long long u64;

// ---- packed f32x2 helpers ----
__device__ __forceinline__ u64 pk2(float lo, float hi) {
    u64 r; asm("mov.b64 %0,{%1,%2};" : "=l"(r) : "f"(lo), "f"(hi)); return r;
}
__device__ __forceinline__ u64 pkd(float x) {
    u64 r; asm("mov.b64 %0,{%1,%1};" : "=l"(r) : "f"(x)); return r;
}
__device__ __forceinline__ void up2(u64 v, float& lo, float& hi) {
    asm("mov.b64 {%0,%1},%2;" : "=f"(lo), "=f"(hi) : "l"(v));
}
__device__ __forceinline__ u64 ffma2(u64 a, u64 b, u64 c) {
    u64 d; asm("fma.rn.f32x2 %0,%1,%2,%3;" : "=l"(d) : "l"(a), "l"(b), "l"(c)); return d;
}

// ---- tables + scratch ----
__device__ float tw[NSK*MM];          // softmax(q_s . K^T) per skill
__device__ float tea[2*NSK*DVX*2];    // interleaved (e,a) per interaction id: [(vi*64+v)*2]
__device__ float qW[NSK*HHX];         // skill_embed[s] @ W1_top + b1
__device__ float g_read[NITEMS*DVX];

// ============================================================================
// Kernel 0: build all tables (round-3 structure). Roles by blockIdx:
//   [0,125)   role A: tw    (8 skills/block, 1 per warp)
//   [125,375) role B: tea   (8 vis/block, 1 per warp)
//   [375,407) role C: qW    (32 skills/block, 4 per warp)
// ============================================================================
__global__ __launch_bounds__(256) void k0_tables(
    const float* __restrict__ skill_embed,
    const float* __restrict__ key_memory,
    const float* __restrict__ interaction_embed,
    const float* __restrict__ erase_W,
    const float* __restrict__ erase_b,
    const float* __restrict__ add_W,
    const float* __restrict__ add_b,
    const float* __restrict__ fc1_W,
    const float* __restrict__ fc1_b)
{
    extern __shared__ float smem[];
    int tid  = threadIdx.x;
    int w    = tid >> 5;
    int lane = tid & 31;
    int bid  = blockIdx.x;

    if (bid < 125) {
        // ---------------- role A: attention softmax table ----------------
        float* sKt = smem;            // [64][52] transposed
        float* sq  = sKt + DKX*52;    // [8 warps][64]
        for (int idx = tid; idx < MM*DKX; idx += 256) {
            int m = idx / DKX, i = idx % DKX;
            sKt[i*52 + m] = key_memory[m*DKX + i];
        }
        __syncthreads();
        int s = bid*8 + w;            // < 1000 always
        float* mq = sq + w*64;
        mq[lane]    = skill_embed[s*DKX + lane];
        mq[lane+32] = skill_embed[s*DKX + lane+32];
        __syncwarp();
        const bool v1 = (lane + 32) < MM;
        float d0 = 0.f, d1 = 0.f;
        #pragma unroll 8
        for (int i = 0; i < DKX; i++) {
            float qi = mq[i];
            d0 = fmaf(qi, sKt[i*52 + lane], d0);
            d1 = fmaf(qi, sKt[i*52 + lane + 32], d1);
        }
        float mx = fmaxf(d0, v1 ? d1 : -1e30f);
        #pragma unroll
        for (int off = 16; off > 0; off >>= 1)
            mx = fmaxf(mx, __shfl_xor_sync(0xffffffffu, mx, off));
        float x0 = __expf(d0 - mx);
        float x1 = v1 ? __expf(d1 - mx) : 0.f;
        float sm = x0 + x1;
        #pragma unroll
        for (int off = 16; off > 0; off >>= 1)
            sm += __shfl_xor_sync(0xffffffffu, sm, off);
        float inv = 1.f / sm;
        tw[s*MM + lane] = x0 * inv;
        if (v1) tw[s*MM + lane + 32] = x1 * inv;
    } else if (bid < 375) {
        // ---------------- role B: gate table (interleaved e,a) ----------------
        float* seW = smem;            // [64*64]
        float* saW = seW + DKX*DVX;   // [64*64]
        float* sv  = saW + DKX*DVX;   // [8 warps][64]
        for (int idx = tid; idx < DKX*DVX; idx += 256) {
            seW[idx] = erase_W[idx];
            saW[idx] = add_W[idx];
        }
        __syncthreads();
        int vi = (bid - 125)*8 + w;   // < 2000
        float* mv = sv + w*64;
        mv[lane]    = interaction_embed[vi*DVX + lane];
        mv[lane+32] = interaction_embed[vi*DVX + lane+32];
        __syncwarp();
        float E0 = erase_b[lane], E1 = erase_b[lane+32];
        float A0 = add_b[lane],   A1 = add_b[lane+32];
        #pragma unroll 8
        for (int i = 0; i < DVX; i++) {
            float vv = mv[i];
            E0 = fmaf(vv, seW[i*DVX + lane],    E0);
            E1 = fmaf(vv, seW[i*DVX + lane+32], E1);
            A0 = fmaf(vv, saW[i*DVX + lane],    A0);
            A1 = fmaf(vv, saW[i*DVX + lane+32], A1);
        }
        float2 ea0 = make_float2(1.f/(1.f + __expf(-E0)), tanhf(A0));
        float2 ea1 = make_float2(1.f/(1.f + __expf(-E1)), tanhf(A1));
        *(float2*)&tea[(vi*DVX + lane)*2]      = ea0;
        *(float2*)&tea[(vi*DVX + lane+32)*2]   = ea1;
    } else {
        // ---------------- role C: qW table ----------------
        float* sW1t = smem;            // [64][128] top rows of fc1_W
        float* sb1  = sW1t + 64*HHX;   // [128]
        float* sq   = sb1 + HHX;       // [8 warps][256] layout [i*4+k]
        for (int idx = tid; idx < 64*HHX; idx += 256) sW1t[idx] = fc1_W[idx];
        if (tid < HHX) sb1[tid] = fc1_b[tid];
        __syncthreads();
        int sbase = (bid - 375)*32 + w*4;
        float* mq = sq + w*256;
        #pragma unroll
        for (int k = 0; k < 4; k++) {
            int s = sbase + k; if (s >= NSK) s = NSK-1;
            mq[lane*4 + k]      = skill_embed[s*DKX + lane];
            mq[(lane+32)*4 + k] = skill_embed[s*DKX + lane+32];
        }
        __syncwarp();
        u64 acc2[4][2];
        #pragma unroll
        for (int c = 0; c < 4; c++) {
            u64 bb = pkd(sb1[lane*4 + c]);
            acc2[c][0] = bb; acc2[c][1] = bb;
        }
        #pragma unroll 4
        for (int i = 0; i < DKX; i++) {
            u64 q01 = *(const u64*)&mq[i*4];
            u64 q23 = *(const u64*)&mq[i*4 + 2];
            float4 w4 = *(const float4*)&sW1t[i*HHX + lane*4];
            u64 wx = pkd(w4.x), wy = pkd(w4.y), wz = pkd(w4.z), wq = pkd(w4.w);
            acc2[0][0] = ffma2(q01, wx, acc2[0][0]);
            acc2[0][1] = ffma2(q23, wx, acc2[0][1]);
            acc2[1][0] = ffma2(q01, wy, acc2[1][0]);
            acc2[1][1] = ffma2(q23, wy, acc2[1][1]);
            acc2[2][0] = ffma2(q01, wz, acc2[2][0]);
            acc2[2][1] = ffma2(q23, wz, acc2[2][1]);
            acc2[3][0] = ffma2(q01, wq, acc2[3][0]);
            acc2[3][1] = ffma2(q23, wq, acc2[3][1]);
        }
        float A[4][4];
        #pragma unroll
        for (int c = 0; c < 4; c++) {
            up2(acc2[c][0], A[c][0], A[c][1]);
            up2(acc2[c][1], A[c][2], A[c][3]);
        }
        #pragma unroll
        for (int k = 0; k < 4; k++) {
            int s = sbase + k;
            if (s < NSK) {
                float4 o = make_float4(A[0][k], A[1][k], A[2][k], A[3][k]);
                *(float4*)&qW[s*HHX + lane*4] = o;
            }
        }
    }
}

// ============================================================================
// Kernel 2: sequential memory scan (round-3 structure + depth-2 prefetch).
// One block per batch, 64 threads; thread = DV column, 25 f32x2 row-pairs
// in registers. w double-buffered in smem (read as LDS.128); (e,a) loaded
// as one float2. Tables prefetched 2 steps ahead to cover L2 latency.
// ============================================================================
__global__ __launch_bounds__(64) void k2_scan(
    const float* __restrict__ value_init,
    const int*   __restrict__ skill_seq,
    const int*   __restrict__ correct_seq)
{
    __shared__ __align__(16) float sw[2][56];   // 56 floats -> 16B-aligned buffers
    __shared__ int ss[TT];
    __shared__ int svi[TT];
    int b = blockIdx.x;
    int v = threadIdx.x;          // 0..63 = DV column
    const int base = b * TT;

    for (int i = v; i < TT; i += 64) {
        int s = skill_seq[base + i];
        ss[i]  = s;
        svi[i] = s + correct_seq[base + i]*NSK;
    }
    if (v >= MM && v < 52) { sw[0][v] = 0.f; sw[1][v] = 0.f; }  // pad pair 25

    u64 mem[25];
    #pragma unroll
    for (int m = 0; m < 25; m++)
        mem[m] = pk2(value_init[(2*m)*DVX + v], value_init[(2*m+1)*DVX + v]);
    __syncthreads();

    // depth-2 prefetch pipeline
    int s0 = ss[0], vi0 = svi[0];
    float  wA  = (v < MM) ? tw[s0*MM + v] : 0.f;
    float2 eaA = *(const float2*)&tea[(vi0*DVX + v)*2];
    int s1 = ss[1], vi1 = svi[1];
    float  wB  = (v < MM) ? tw[s1*MM + v] : 0.f;
    float2 eaB = *(const float2*)&tea[(vi1*DVX + v)*2];

    for (int t = 0; t < TT; t++) {
        if (v < MM) sw[t & 1][v] = wA;
        float e = eaA.x, a = eaA.y;
        __syncthreads();
        wA = wB; eaA = eaB;
        if (t + 2 < TT) {
            int s2 = ss[t+2], vi2 = svi[t+2];
            wB  = (v < MM) ? tw[s2*MM + v] : 0.f;
            eaB = *(const float2*)&tea[(vi2*DVX + v)*2];
        }
        u64 nee = pkd(-e);
        u64 aa  = pkd(a);
        const float* swc = sw[t & 1];
        u64 r[4] = {0ull,0ull,0ull,0ull};
        #pragma unroll
        for (int i = 0; i < 12; i++) {          // pairs 2i, 2i+1 via LDS.128
            float4 w4 = *(const float4*)&swc[4*i];
            u64 wlo = pk2(w4.x, w4.y);
            u64 whi = pk2(w4.z, w4.w);
            int m = 2*i;
            r[m & 3]     = ffma2(wlo, mem[m],   r[m & 3]);
            u64 t1       = ffma2(mem[m],   nee, aa);
            mem[m]       = ffma2(wlo, t1,  mem[m]);
            r[(m+1) & 3] = ffma2(whi, mem[m+1], r[(m+1) & 3]);
            u64 t2       = ffma2(mem[m+1], nee, aa);
            mem[m+1]     = ffma2(whi, t2,  mem[m+1]);
        }
        {   // pair 24
            u64 ww = *(const u64*)&swc[48];
            r[0]    = ffma2(ww, mem[24], r[0]);
            u64 t1  = ffma2(mem[24], nee, aa);
            mem[24] = ffma2(ww, t1, mem[24]);
        }
        float x0, x1, y0, y1, z0, z1, u0, u1;
        up2(r[0], x0, x1); up2(r[1], y0, y1);
        up2(r[2], z0, z1); up2(r[3], u0, u1);
        g_read[(base + t)*DVX + v] = ((x0+x1) + (y0+y1)) + ((z0+z1) + (u0+u1));
    }
}

// ============================================================================
// Kernel 3: output MLP, read-half only (round-3 code): h = relu(qW[s] +
// read @ W1_low); logit = h @ w2 + b2. W1_low in shared; one warp per 8 items.
// ============================================================================
__global__ __launch_bounds__(256,3) void k3_mlp(
    const int*   __restrict__ skill_seq,
    const int*   __restrict__ correct_seq,
    const float* __restrict__ mask,
    const float* __restrict__ fc1_W,
    const float* __restrict__ fc2_W,
    const float* __restrict__ fc2_b,
    float*       __restrict__ out)
{
    extern __shared__ float smem[];
    float* sW1 = smem;                    // [64][128] = fc1_W rows 64..127
    float* sw2 = sW1 + 64*HHX;            // [128]
    float* sx  = sw2 + HHX;               // [8 warps][64*10]

    int tid = threadIdx.x;
    for (int idx = tid; idx < 64*HHX; idx += 256) sW1[idx] = fc1_W[64*HHX + idx];
    if (tid < HHX) sw2[tid] = fc2_W[tid];
    __syncthreads();
    float b2 = fc2_b[0];

    int w    = tid >> 5;
    int lane = tid & 31;
    float* myx = sx + w * (64 * 10);

    const int nwarps  = gridDim.x * 8;
    const int ngroups = NITEMS / 8;

    for (int g = blockIdx.x*8 + w; g < ngroups; g += nwarps) {
        int base = g * 8;
        float4 qk[8];
        #pragma unroll
        for (int k = 0; k < 8; k++) {
            int item = base + k;
            int s = skill_seq[item];
            qk[k] = *(const float4*)&qW[s*HHX + lane*4];
            myx[(lane)    *10 + k] = g_read[item*DVX + lane];
            myx[(lane+32) *10 + k] = g_read[item*DVX + lane+32];
        }
        __syncwarp();

        u64 acc[4][4];   // [c][item-pair]
        #pragma unroll
        for (int kk = 0; kk < 4; kk++) {
            acc[0][kk] = pk2(qk[2*kk].x, qk[2*kk+1].x);
            acc[1][kk] = pk2(qk[2*kk].y, qk[2*kk+1].y);
            acc[2][kk] = pk2(qk[2*kk].z, qk[2*kk+1].z);
            acc[3][kk] = pk2(qk[2*kk].w, qk[2*kk+1].w);
        }
        #pragma unroll 4
        for (int j = 0; j < 64; j++) {
            float4 wv = *(const float4*)&sW1[j*HHX + lane*4];
            u64 xp[4];
            #pragma unroll
            for (int kk = 0; kk < 4; kk++)
                xp[kk] = *(const u64*)&myx[j*10 + 2*kk];
            u64 wx = pkd(wv.x), wy = pkd(wv.y), wz = pkd(wv.z), wq = pkd(wv.w);
            #pragma unroll
            for (int kk = 0; kk < 4; kk++) {
                acc[0][kk] = ffma2(xp[kk], wx, acc[0][kk]);
                acc[1][kk] = ffma2(xp[kk], wy, acc[1][kk]);
                acc[2][kk] = ffma2(xp[kk], wz, acc[2][kk]);
                acc[3][kk] = ffma2(xp[kk], wq, acc[3][kk]);
            }
        }
        float hv[4][8];
        #pragma unroll
        for (int c = 0; c < 4; c++) {
            #pragma unroll
            for (int kk = 0; kk < 4; kk++)
                up2(acc[c][kk], hv[c][2*kk], hv[c][2*kk+1]);
        }
        float part[8];
        #pragma unroll
        for (int k = 0; k < 8; k++) {
            float p = 0.f;
            #pragma unroll
            for (int c = 0; c < 4; c++) {
                float h = fmaxf(hv[c][k], 0.f);
                p = fmaf(h, sw2[lane*4 + c], p);
            }
            part[k] = p;
        }
        #pragma unroll
        for (int off = 16; off > 0; off >>= 1) {
            #pragma unroll
            for (int k = 0; k < 8; k++)
                part[k] += __shfl_xor_sync(0xffffffffu, part[k], off);
        }
        if (lane < 8) {
            int item = base + lane;
            float logit = part[lane] + b2;
            float p = 1.f / (1.f + __expf(-logit));
            float mk = mask[item];
            out[item]          = p * mk;
            out[NITEMS + item] = (float)correct_seq[item] * mk;
        }
        __syncwarp();
    }
}

// ============================================================================
extern "C" void kernel_launch(void* const* d_in, const int* in_sizes, int n_in,
                              void* d_out, int out_size) {
    const int*   skill_seq         = (const int*)  d_in[0];
    const int*   correct_seq       = (const int*)  d_in[1];
    const float* mask              = (const float*)d_in[2];
    const float* skill_embed       = (const float*)d_in[3];
    const float* key_memory        = (const float*)d_in[4];
    const float* value_init        = (const float*)d_in[5];
    const float* interaction_embed = (const float*)d_in[6];
    const float* erase_W           = (const float*)d_in[7];
    const float* erase_b           = (const float*)d_in[8];
    const float* add_W             = (const float*)d_in[9];
    const float* add_b             = (const float*)d_in[10];
    const float* fc1_W             = (const float*)d_in[11];
    const float* fc1_b             = (const float*)d_in[12];
    const float* fc2_W             = (const float*)d_in[13];
    const float* fc2_b             = (const float*)d_in[14];
    float* out = (float*)d_out;

    const int k0_smem = (64*HHX + HHX + 8*256) * sizeof(float);            // ~41.5 KB
    const int k3_smem = (64*HHX + HHX + 8*64*10) * sizeof(float);          // ~53 KB
    cudaFuncSetAttribute(k3_mlp, cudaFuncAttributeMaxDynamicSharedMemorySize, k3_smem);

    k0_tables<<<407, 256, k0_smem>>>(skill_embed, key_memory, interaction_embed,
                                     erase_W, erase_b, add_W, add_b, fc1_W, fc1_b);
    k2_scan<<<BB, 64>>>(value_init, skill_seq, correct_seq);
    k3_mlp<<<444, 256, k3_smem>>>(skill_seq, correct_seq, mask,
                                  fc1_W, fc2_W, fc2_b, out);
}